// round 14
// baseline (speedup 1.0000x reference)
#include <cuda_runtime.h>
#include <cuda_fp16.h>
#include <cstdint>

// ============================================================================
// out[B, OUT] = x[B, IN] @ W[OUT, IN]^T + b[OUT], fp32, 4096^3.
// Plain sm_103 target -> fp16 HMMA single pass (products exact in fp32).
// R14: tail-only tile splitting. Tiles 0..887 full 128x128 (3 clean waves);
//      tiles 888..1023 run as two 128x64 half-CTAs (full K, disjoint N) so
//      the 4th wave takes T/2 instead of T. Makespan 4T -> 3.5T.
//      GEMM core otherwise identical to R13 (303.4us measured).
// ============================================================================

#define DIM 4096

__device__ __half g_xh[(size_t)DIM * DIM];
__device__ __half g_wh[(size_t)DIM * DIM];

// ----------------------------------------------------------------------------
// helpers
// ----------------------------------------------------------------------------
__device__ __forceinline__ uint32_t smem_u32(const void* p) {
    uint32_t a;
    asm("{ .reg .u64 t; cvta.to.shared.u64 t, %1; cvt.u32.u64 %0, t; }"
        : "=r"(a) : "l"(p));
    return a;
}

__device__ __forceinline__ void cp16(uint32_t dst, const void* src) {
    asm volatile("cp.async.cg.shared.global [%0], [%1], 16;"
                 :: "r"(dst), "l"(src));
}
#define CP_COMMIT() asm volatile("cp.async.commit_group;" ::: "memory")
#define CP_WAIT()   asm volatile("cp.async.wait_group 1;"  ::: "memory")

__device__ __forceinline__ void ldm4(uint32_t* r, uint32_t addr) {
    asm volatile("ldmatrix.sync.aligned.m8n8.x4.shared.b16 {%0,%1,%2,%3}, [%4];"
                 : "=r"(r[0]), "=r"(r[1]), "=r"(r[2]), "=r"(r[3]) : "r"(addr));
}

__device__ __forceinline__ void mma16816(float* d, const uint32_t* a, const uint32_t* b) {
    asm volatile(
        "mma.sync.aligned.m16n8k16.row.col.f32.f16.f16.f32 "
        "{%0,%1,%2,%3}, {%4,%5,%6,%7}, {%8,%9}, {%0,%1,%2,%3};"
        : "+f"(d[0]), "+f"(d[1]), "+f"(d[2]), "+f"(d[3])
        : "r"(a[0]), "r"(a[1]), "r"(a[2]), "r"(a[3]), "r"(b[0]), "r"(b[1]));
}

// ----------------------------------------------------------------------------
// Kernel 1: fp32 -> fp16 (R13 version: streaming, uniform branch, no loop)
// ----------------------------------------------------------------------------
__global__ void __launch_bounds__(256)
convert_half(const float* __restrict__ x, const float* __restrict__ W) {
    const bool isw = blockIdx.x >= 8192;
    const float4* __restrict__ src = (const float4*)(isw ? W : x);
    uint2* __restrict__ dst = (uint2*)(isw ? g_wh : g_xh);
    const int base = (isw ? blockIdx.x - 8192 : blockIdx.x) * 512 + threadIdx.x;
#pragma unroll
    for (int i = 0; i < 2; i++) {
        const int j = base + i * 256;
        float4 f = __ldcs(src + j);
        __half2 h0 = __floats2half2_rn(f.x, f.y);
        __half2 h1 = __floats2half2_rn(f.z, f.w);
        uint2 pk;
        pk.x = *(const uint32_t*)&h0;
        pk.y = *(const uint32_t*)&h1;
        __stcs(dst + j, pk);
    }
}

// ----------------------------------------------------------------------------
// Kernel 2: fp16 HMMA GEMM. Full CTAs: 128x128x64, 3 stages, 4 warps (2x2),
// 2 CTAs/SM (R13 core). Tail CTAs: 128x64 (full K, half N, same layout).
// ----------------------------------------------------------------------------
static constexpr int BM = 128;
static constexpr int BN = 128;
static constexpr int BK = 64;                    // fp16 elems (128B rows)
static constexpr int NK = DIM / BK;              // 64 iterations
static constexpr int NTHREADS = 128;
static constexpr int FULL_TILES = 888;           // 3 clean waves @296 or @304 slots
static constexpr int TOTAL_TILES = 1024;
static constexpr int GRID = FULL_TILES + 2 * (TOTAL_TILES - FULL_TILES);  // 1160

static constexpr int A_B = BM * BK * 2;          // 16384
static constexpr int B_B = BN * BK * 2;          // 16384
static constexpr int OFF_A = 0;
static constexpr int OFF_B = A_B;
static constexpr int STAGE_B = A_B + B_B;        // 32768
static constexpr int STAGES = 3;
static constexpr int SMEM_BYTES = STAGES * STAGE_B;  // 98304 -> 2 CTAs/SM

// SW128 swizzle: row r (128B rows), 16B unit u in [0,8)
__device__ __forceinline__ uint32_t sw_off(int r, int u) {
    return (uint32_t)(r * 128 + ((u ^ (r & 7)) << 4));
}

// A: 128 rows -> 1024 units -> 8 per thread (both CTA kinds)
__device__ __forceinline__ void load_A(uint32_t st, int tm, int k0, int tid) {
#pragma unroll
    for (int i = 0; i < 8; i++) {
        int c = tid + i * NTHREADS;
        int r = c >> 3, u = c & 7;
        cp16(st + OFF_A + sw_off(r, u),
             g_xh + (size_t)(tm * BM + r) * DIM + k0 + u * 8);
    }
}
// B full: 128 rows -> 8 per thread
__device__ __forceinline__ void load_B_full(uint32_t st, int n0, int k0, int tid) {
#pragma unroll
    for (int i = 0; i < 8; i++) {
        int c = tid + i * NTHREADS;
        int r = c >> 3, u = c & 7;
        cp16(st + OFF_B + sw_off(r, u),
             g_wh + (size_t)(n0 + r) * DIM + k0 + u * 8);
    }
}
// B half: 64 rows -> 4 per thread
__device__ __forceinline__ void load_B_half(uint32_t st, int n0, int k0, int tid) {
#pragma unroll
    for (int i = 0; i < 4; i++) {
        int c = tid + i * NTHREADS;
        int r = c >> 3, u = c & 7;
        cp16(st + OFF_B + sw_off(r, u),
             g_wh + (size_t)(n0 + r) * DIM + k0 + u * 8);
    }
}

__global__ void __launch_bounds__(NTHREADS, 2)
gemm_kernel(const float* __restrict__ bias, float* __restrict__ out) {
    extern __shared__ char smem[];
    const uint32_t sb = smem_u32(smem);
    const int tid = threadIdx.x;
    const int wid = tid >> 5;
    const int lane = tid & 31;
    const int warp_m = wid & 1;      // 2 warps along M (64 rows each)
    const int warp_n = wid >> 1;     // 2 warps along N

    // Tile mapping: bids < 888 -> full tiles; bids >= 888 -> N-half tiles.
    const int bid = blockIdx.x;
    const bool full = bid < FULL_TILES;
    int tile, nh;
    if (full) { tile = bid; nh = 0; }
    else { const int idx = bid - FULL_TILES; tile = FULL_TILES + (idx >> 1); nh = idx & 1; }
    const int tm = tile & 31;
    const int tn = tile >> 5;
    const int bn0 = tn * BN + (full ? 0 : nh * 64);   // base N of this CTA's B tile
    const int b_seg = full ? warp_n * 64 : warp_n * 32;

    // ldmatrix lane addressing, 128B rows (proven fragment map).
    const int a_idx = lane >> 3;
    const int a_row = warp_m * 64 + (lane & 7) + (a_idx & 1) * 8;
    const int a_kk  = a_idx >> 1;
    const int b_idx = lane >> 3;
    const int b_row = b_seg + (lane & 7) + (b_idx >> 1) * 8;
    const int b_kk  = b_idx & 1;
    const int lsw   = lane & 7;

    uint32_t ua[4], ub[4];
#pragma unroll
    for (int ks = 0; ks < 4; ks++) {
        ua[ks] = (uint32_t)(((ks * 2 + a_kk) ^ lsw) << 4);
        ub[ks] = (uint32_t)(((ks * 2 + b_kk) ^ lsw) << 4);
    }
    const uint32_t a_base = (uint32_t)(a_row * 128);   // + mt*2048
    const uint32_t b_base = (uint32_t)(b_row * 128);   // + p*2048

    float acc[4][8][4];
#pragma unroll
    for (int mt = 0; mt < 4; mt++)
#pragma unroll
        for (int nt = 0; nt < 8; nt++)
#pragma unroll
            for (int j = 0; j < 4; j++) acc[mt][nt][j] = 0.f;

    // Prologue: fill STAGES-1 = 2 stages
#pragma unroll
    for (int s = 0; s < STAGES - 1; s++) {
        const uint32_t st = sb + s * STAGE_B;
        load_A(st, tm, s * BK, tid);
        if (full) load_B_full(st, bn0, s * BK, tid);
        else      load_B_half(st, bn0, s * BK, tid);
        CP_COMMIT();
    }

    int s_cur = 0;
    int s_nxt = STAGES - 1;
    for (int kt = 0; kt < NK; kt++) {
        CP_WAIT();
        __syncthreads();

        const int kn = kt + STAGES - 1;
        if (kn < NK) {
            const uint32_t st = sb + s_nxt * STAGE_B;
            load_A(st, tm, kn * BK, tid);
            if (full) load_B_full(st, bn0, kn * BK, tid);
            else      load_B_half(st, bn0, kn * BK, tid);
        }
        CP_COMMIT();   // unconditional: keeps wait_group accounting exact

        const uint32_t stg = sb + s_cur * STAGE_B;
        if (full) {
#pragma unroll
            for (int ks = 0; ks < 4; ks++) {
                uint32_t a[4][4];
#pragma unroll
                for (int mt = 0; mt < 4; mt++)
                    ldm4(a[mt], stg + OFF_A + a_base + mt * 2048 + ua[ks]);
                uint32_t b[4][4];
#pragma unroll
                for (int p = 0; p < 4; p++)
                    ldm4(b[p], stg + OFF_B + b_base + p * 2048 + ub[ks]);
#pragma unroll
                for (int mt = 0; mt < 4; mt++) {
#pragma unroll
                    for (int nt = 0; nt < 8; nt++) {
                        const int p = nt >> 1, h = (nt & 1) * 2;
                        mma16816(acc[mt][nt], a[mt], &b[p][h]);
                    }
                }
            }
        } else {
#pragma unroll
            for (int ks = 0; ks < 4; ks++) {
                uint32_t a[4][4];
#pragma unroll
                for (int mt = 0; mt < 4; mt++)
                    ldm4(a[mt], stg + OFF_A + a_base + mt * 2048 + ua[ks]);
                uint32_t b[2][4];
#pragma unroll
                for (int p = 0; p < 2; p++)
                    ldm4(b[p], stg + OFF_B + b_base + p * 2048 + ub[ks]);
#pragma unroll
                for (int mt = 0; mt < 4; mt++) {
#pragma unroll
                    for (int nt = 0; nt < 4; nt++) {
                        const int p = nt >> 1, h = (nt & 1) * 2;
                        mma16816(acc[mt][nt], a[mt], &b[p][h]);
                    }
                }
            }
        }

        if (++s_cur == STAGES) s_cur = 0;
        if (++s_nxt == STAGES) s_nxt = 0;
    }

    // Epilogue: add bias, store fp32
    const int m0 = tm * BM + warp_m * 64;
    const int n0 = bn0 + b_seg;
    const int er = lane >> 2;
    const int ec = (lane & 3) * 2;
    const int nt_max = full ? 8 : 4;
#pragma unroll 4
    for (int nt = 0; nt < nt_max; nt++) {
        const int col = n0 + nt * 8 + ec;
        const float b0 = __ldg(bias + col);
        const float b1 = __ldg(bias + col + 1);
#pragma unroll
        for (int mt = 0; mt < 4; mt++) {
            const int row = m0 + mt * 16 + er;
            float2 v0 = make_float2(acc[mt][nt][0] + b0, acc[mt][nt][1] + b1);
            float2 v1 = make_float2(acc[mt][nt][2] + b0, acc[mt][nt][3] + b1);
            *(float2*)(out + (size_t)row * DIM + col) = v0;
            *(float2*)(out + (size_t)(row + 8) * DIM + col) = v1;
        }
    }
}

// ----------------------------------------------------------------------------
// kernel_launch
// ----------------------------------------------------------------------------
extern "C" void kernel_launch(void* const* d_in, const int* in_sizes, int n_in,
                              void* d_out, int out_size) {
    const float* x = (const float*)d_in[0];
    const float* W = (const float*)d_in[1];
    const float* b = (const float*)d_in[2];
    float* out = (float*)d_out;

    cudaFuncSetAttribute(gemm_kernel,
                         cudaFuncAttributeMaxDynamicSharedMemorySize, SMEM_BYTES);

    convert_half<<<16384, 256>>>(x, W);

    gemm_kernel<<<GRID, NTHREADS, SMEM_BYTES>>>(b, out);
}

// round 15
// speedup vs baseline: 6.0934x; 6.0934x over previous
#include <cuda_runtime.h>
#include <cuda_fp16.h>
#include <cstdint>

// ============================================================================
// out[B, OUT] = x[B, IN] @ W[OUT, IN]^T + b[OUT], fp32, 4096^3.
// Plain sm_103 target -> fp16 HMMA single pass (products exact in fp32).
// R15: tail splitting via TWO UNIFORM KERNELS (R14's intra-kernel divergence
//      caused 255-reg spills). Kernel A = R13 core verbatim, grid=888 (3
//      clean waves). Kernel B = 272 half-N CTAs (128x64, full K) for tiles
//      888..1023. Makespan 4T -> ~3.6T.
// ============================================================================

#define DIM 4096

__device__ __half g_xh[(size_t)DIM * DIM];
__device__ __half g_wh[(size_t)DIM * DIM];

// ----------------------------------------------------------------------------
// helpers
// ----------------------------------------------------------------------------
__device__ __forceinline__ uint32_t smem_u32(const void* p) {
    uint32_t a;
    asm("{ .reg .u64 t; cvta.to.shared.u64 t, %1; cvt.u32.u64 %0, t; }"
        : "=r"(a) : "l"(p));
    return a;
}

__device__ __forceinline__ void cp16(uint32_t dst, const void* src) {
    asm volatile("cp.async.cg.shared.global [%0], [%1], 16;"
                 :: "r"(dst), "l"(src));
}
#define CP_COMMIT() asm volatile("cp.async.commit_group;" ::: "memory")
#define CP_WAIT()   asm volatile("cp.async.wait_group 1;"  ::: "memory")

__device__ __forceinline__ void ldm4(uint32_t* r, uint32_t addr) {
    asm volatile("ldmatrix.sync.aligned.m8n8.x4.shared.b16 {%0,%1,%2,%3}, [%4];"
                 : "=r"(r[0]), "=r"(r[1]), "=r"(r[2]), "=r"(r[3]) : "r"(addr));
}

__device__ __forceinline__ void mma16816(float* d, const uint32_t* a, const uint32_t* b) {
    asm volatile(
        "mma.sync.aligned.m16n8k16.row.col.f32.f16.f16.f32 "
        "{%0,%1,%2,%3}, {%4,%5,%6,%7}, {%8,%9}, {%0,%1,%2,%3};"
        : "+f"(d[0]), "+f"(d[1]), "+f"(d[2]), "+f"(d[3])
        : "r"(a[0]), "r"(a[1]), "r"(a[2]), "r"(a[3]), "r"(b[0]), "r"(b[1]));
}

// ----------------------------------------------------------------------------
// Kernel 1: fp32 -> fp16 (R13 version: streaming, uniform branch, no loop)
// ----------------------------------------------------------------------------
__global__ void __launch_bounds__(256)
convert_half(const float* __restrict__ x, const float* __restrict__ W) {
    const bool isw = blockIdx.x >= 8192;
    const float4* __restrict__ src = (const float4*)(isw ? W : x);
    uint2* __restrict__ dst = (uint2*)(isw ? g_wh : g_xh);
    const int base = (isw ? blockIdx.x - 8192 : blockIdx.x) * 512 + threadIdx.x;
#pragma unroll
    for (int i = 0; i < 2; i++) {
        const int j = base + i * 256;
        float4 f = __ldcs(src + j);
        __half2 h0 = __floats2half2_rn(f.x, f.y);
        __half2 h1 = __floats2half2_rn(f.z, f.w);
        uint2 pk;
        pk.x = *(const uint32_t*)&h0;
        pk.y = *(const uint32_t*)&h1;
        __stcs(dst + j, pk);
    }
}

// ----------------------------------------------------------------------------
// Shared tiling constants
// ----------------------------------------------------------------------------
static constexpr int BM = 128;
static constexpr int BN = 128;
static constexpr int BK = 64;                    // fp16 elems (128B rows)
static constexpr int NK = DIM / BK;              // 64 iterations
static constexpr int NTHREADS = 128;
static constexpr int FULL_TILES = 888;           // 3 clean waves of 296
static constexpr int TOTAL_TILES = 1024;

// SW128 swizzle: row r (128B rows), 16B unit u in [0,8)
__device__ __forceinline__ uint32_t sw_off(int r, int u) {
    return (uint32_t)(r * 128 + ((u ^ (r & 7)) << 4));
}

__device__ __forceinline__ void load_rows128(uint32_t st, const __half* gsrc,
                                             int row0, int k0, int tid) {
#pragma unroll
    for (int i = 0; i < 8; i++) {
        int c = tid + i * NTHREADS;
        int r = c >> 3, u = c & 7;
        cp16(st + sw_off(r, u), gsrc + (size_t)(row0 + r) * DIM + k0 + u * 8);
    }
}
__device__ __forceinline__ void load_rows64(uint32_t st, const __half* gsrc,
                                            int row0, int k0, int tid) {
#pragma unroll
    for (int i = 0; i < 4; i++) {
        int c = tid + i * NTHREADS;
        int r = c >> 3, u = c & 7;
        cp16(st + sw_off(r, u), gsrc + (size_t)(row0 + r) * DIM + k0 + u * 8);
    }
}

// ----------------------------------------------------------------------------
// Kernel A: full 128x128 tiles (R13 core verbatim), grid = 888.
// ----------------------------------------------------------------------------
static constexpr int A_B = BM * BK * 2;          // 16384
static constexpr int B_B = BN * BK * 2;          // 16384
static constexpr int STAGE_F = A_B + B_B;        // 32768
static constexpr int STAGES = 3;
static constexpr int SMEM_F = STAGES * STAGE_F;  // 98304 -> 2 CTAs/SM

__global__ void __launch_bounds__(NTHREADS, 2)
gemm_full(const float* __restrict__ bias, float* __restrict__ out) {
    extern __shared__ char smem[];
    const uint32_t sb = smem_u32(smem);
    const int tid = threadIdx.x;
    const int wid = tid >> 5;
    const int lane = tid & 31;
    const int warp_m = wid & 1;
    const int warp_n = wid >> 1;

    const int bid = blockIdx.x;
    const int tm = bid & 31;
    const int tn = bid >> 5;

    const int a_idx = lane >> 3;
    const int a_row = warp_m * 64 + (lane & 7) + (a_idx & 1) * 8;
    const int a_kk  = a_idx >> 1;
    const int b_idx = lane >> 3;
    const int b_row = warp_n * 64 + (lane & 7) + (b_idx >> 1) * 8;
    const int b_kk  = b_idx & 1;
    const int lsw   = lane & 7;

    uint32_t ua[4], ub[4];
#pragma unroll
    for (int ks = 0; ks < 4; ks++) {
        ua[ks] = (uint32_t)(((ks * 2 + a_kk) ^ lsw) << 4);
        ub[ks] = (uint32_t)(((ks * 2 + b_kk) ^ lsw) << 4);
    }
    const uint32_t a_base = (uint32_t)(a_row * 128);
    const uint32_t b_base = (uint32_t)(b_row * 128);

    float acc[4][8][4];
#pragma unroll
    for (int mt = 0; mt < 4; mt++)
#pragma unroll
        for (int nt = 0; nt < 8; nt++)
#pragma unroll
            for (int j = 0; j < 4; j++) acc[mt][nt][j] = 0.f;

#pragma unroll
    for (int s = 0; s < STAGES - 1; s++) {
        const uint32_t st = sb + s * STAGE_F;
        load_rows128(st, g_xh, tm * BM, s * BK, tid);
        load_rows128(st + A_B, g_wh, tn * BN, s * BK, tid);
        CP_COMMIT();
    }

    int s_cur = 0, s_nxt = STAGES - 1;
    for (int kt = 0; kt < NK; kt++) {
        CP_WAIT();
        __syncthreads();

        const int kn = kt + STAGES - 1;
        if (kn < NK) {
            const uint32_t st = sb + s_nxt * STAGE_F;
            load_rows128(st, g_xh, tm * BM, kn * BK, tid);
            load_rows128(st + A_B, g_wh, tn * BN, kn * BK, tid);
        }
        CP_COMMIT();

        const uint32_t stg = sb + s_cur * STAGE_F;
#pragma unroll
        for (int ks = 0; ks < 4; ks++) {
            uint32_t a[4][4];
#pragma unroll
            for (int mt = 0; mt < 4; mt++)
                ldm4(a[mt], stg + a_base + mt * 2048 + ua[ks]);
            uint32_t b[4][4];
#pragma unroll
            for (int p = 0; p < 4; p++)
                ldm4(b[p], stg + A_B + b_base + p * 2048 + ub[ks]);
#pragma unroll
            for (int mt = 0; mt < 4; mt++) {
#pragma unroll
                for (int nt = 0; nt < 8; nt++) {
                    const int p = nt >> 1, h = (nt & 1) * 2;
                    mma16816(acc[mt][nt], a[mt], &b[p][h]);
                }
            }
        }

        if (++s_cur == STAGES) s_cur = 0;
        if (++s_nxt == STAGES) s_nxt = 0;
    }

    const int m0 = tm * BM + warp_m * 64;
    const int n0 = tn * BN + warp_n * 64;
    const int er = lane >> 2;
    const int ec = (lane & 3) * 2;
#pragma unroll
    for (int nt = 0; nt < 8; nt++) {
        const int col = n0 + nt * 8 + ec;
        const float b0 = __ldg(bias + col);
        const float b1 = __ldg(bias + col + 1);
#pragma unroll
        for (int mt = 0; mt < 4; mt++) {
            const int row = m0 + mt * 16 + er;
            float2 v0 = make_float2(acc[mt][nt][0] + b0, acc[mt][nt][1] + b1);
            float2 v1 = make_float2(acc[mt][nt][2] + b0, acc[mt][nt][3] + b1);
            *(float2*)(out + (size_t)row * DIM + col) = v0;
            *(float2*)(out + (size_t)(row + 8) * DIM + col) = v1;
        }
    }
}

// ----------------------------------------------------------------------------
// Kernel B: half-N tail tiles (128x64, full K), grid = 272.
// Tile t = 888 + (bid>>1), N-half = bid&1. Warp tile 64x32 (R12's proven map).
// ----------------------------------------------------------------------------
static constexpr int BT_B = 64 * BK * 2;         // 8192 (B tile, 64 rows)
static constexpr int STAGE_T = A_B + BT_B;       // 24576
static constexpr int SMEM_T = STAGES * STAGE_T;  // 73728 -> 2 CTAs/SM

__global__ void __launch_bounds__(NTHREADS, 2)
gemm_tail(const float* __restrict__ bias, float* __restrict__ out) {
    extern __shared__ char smem[];
    const uint32_t sb = smem_u32(smem);
    const int tid = threadIdx.x;
    const int wid = tid >> 5;
    const int lane = tid & 31;
    const int warp_m = wid & 1;      // 2 warps along M (64 rows)
    const int warp_n = wid >> 1;     // 2 warps along N (32 cols)

    const int idx = blockIdx.x;
    const int tile = FULL_TILES + (idx >> 1);
    const int nh = idx & 1;
    const int tm = tile & 31;
    const int tn = tile >> 5;
    const int bn0 = tn * BN + nh * 64;

    const int a_idx = lane >> 3;
    const int a_row = warp_m * 64 + (lane & 7) + (a_idx & 1) * 8;
    const int a_kk  = a_idx >> 1;
    const int b_idx = lane >> 3;
    const int b_row = warp_n * 32 + (lane & 7) + (b_idx >> 1) * 8;
    const int b_kk  = b_idx & 1;
    const int lsw   = lane & 7;

    uint32_t ua[4], ub[4];
#pragma unroll
    for (int ks = 0; ks < 4; ks++) {
        ua[ks] = (uint32_t)(((ks * 2 + a_kk) ^ lsw) << 4);
        ub[ks] = (uint32_t)(((ks * 2 + b_kk) ^ lsw) << 4);
    }
    const uint32_t a_base = (uint32_t)(a_row * 128);
    const uint32_t b_base = (uint32_t)(b_row * 128);

    float acc[4][4][4];
#pragma unroll
    for (int mt = 0; mt < 4; mt++)
#pragma unroll
        for (int nt = 0; nt < 4; nt++)
#pragma unroll
            for (int j = 0; j < 4; j++) acc[mt][nt][j] = 0.f;

#pragma unroll
    for (int s = 0; s < STAGES - 1; s++) {
        const uint32_t st = sb + s * STAGE_T;
        load_rows128(st, g_xh, tm * BM, s * BK, tid);
        load_rows64(st + A_B, g_wh, bn0, s * BK, tid);
        CP_COMMIT();
    }

    int s_cur = 0, s_nxt = STAGES - 1;
    for (int kt = 0; kt < NK; kt++) {
        CP_WAIT();
        __syncthreads();

        const int kn = kt + STAGES - 1;
        if (kn < NK) {
            const uint32_t st = sb + s_nxt * STAGE_T;
            load_rows128(st, g_xh, tm * BM, kn * BK, tid);
            load_rows64(st + A_B, g_wh, bn0, kn * BK, tid);
        }
        CP_COMMIT();

        const uint32_t stg = sb + s_cur * STAGE_T;
#pragma unroll
        for (int ks = 0; ks < 4; ks++) {
            uint32_t a[4][4];
#pragma unroll
            for (int mt = 0; mt < 4; mt++)
                ldm4(a[mt], stg + a_base + mt * 2048 + ua[ks]);
            uint32_t b[2][4];
#pragma unroll
            for (int p = 0; p < 2; p++)
                ldm4(b[p], stg + A_B + b_base + p * 2048 + ub[ks]);
#pragma unroll
            for (int mt = 0; mt < 4; mt++) {
#pragma unroll
                for (int nt = 0; nt < 4; nt++) {
                    const int p = nt >> 1, h = (nt & 1) * 2;
                    mma16816(acc[mt][nt], a[mt], &b[p][h]);
                }
            }
        }

        if (++s_cur == STAGES) s_cur = 0;
        if (++s_nxt == STAGES) s_nxt = 0;
    }

    const int m0 = tm * BM + warp_m * 64;
    const int n0 = bn0 + warp_n * 32;
    const int er = lane >> 2;
    const int ec = (lane & 3) * 2;
#pragma unroll
    for (int nt = 0; nt < 4; nt++) {
        const int col = n0 + nt * 8 + ec;
        const float b0 = __ldg(bias + col);
        const float b1 = __ldg(bias + col + 1);
#pragma unroll
        for (int mt = 0; mt < 4; mt++) {
            const int row = m0 + mt * 16 + er;
            float2 v0 = make_float2(acc[mt][nt][0] + b0, acc[mt][nt][1] + b1);
            float2 v1 = make_float2(acc[mt][nt][2] + b0, acc[mt][nt][3] + b1);
            *(float2*)(out + (size_t)row * DIM + col) = v0;
            *(float2*)(out + (size_t)(row + 8) * DIM + col) = v1;
        }
    }
}

// ----------------------------------------------------------------------------
// kernel_launch
// ----------------------------------------------------------------------------
extern "C" void kernel_launch(void* const* d_in, const int* in_sizes, int n_in,
                              void* d_out, int out_size) {
    const float* x = (const float*)d_in[0];
    const float* W = (const float*)d_in[1];
    const float* b = (const float*)d_in[2];
    float* out = (float*)d_out;

    cudaFuncSetAttribute(gemm_full,
                         cudaFuncAttributeMaxDynamicSharedMemorySize, SMEM_F);
    cudaFuncSetAttribute(gemm_tail,
                         cudaFuncAttributeMaxDynamicSharedMemorySize, SMEM_T);

    convert_half<<<16384, 256>>>(x, W);
    gemm_full<<<FULL_TILES, NTHREADS, SMEM_F>>>(b, out);
    gemm_tail<<<2 * (TOTAL_TILES - FULL_TILES), NTHREADS, SMEM_T>>>(b, out);
}

// round 16
// speedup vs baseline: 6.2745x; 1.0297x over previous
#include <cuda_runtime.h>
#include <cuda_fp16.h>
#include <cstdint>

// ============================================================================
// out[B, OUT] = x[B, IN] @ W[OUT, IN]^T + b[OUT], fp32, 4096^3.
// Plain sm_103 target -> fp16 HMMA single pass (products exact in fp32).
// R16: GEMM = R13 core verbatim (303.4us measured; proven plateau).
//      Convert rewritten: 4 independent float4 loads -> 2 uint4 stores per
//      thread (MLP 4, coalesced 16B stores). 30.3us -> ~26us predicted.
// ============================================================================

#define DIM 4096

__device__ __half g_xh[(size_t)DIM * DIM];
__device__ __half g_wh[(size_t)DIM * DIM];

// ----------------------------------------------------------------------------
// helpers
// ----------------------------------------------------------------------------
__device__ __forceinline__ uint32_t smem_u32(const void* p) {
    uint32_t a;
    asm("{ .reg .u64 t; cvta.to.shared.u64 t, %1; cvt.u32.u64 %0, t; }"
        : "=r"(a) : "l"(p));
    return a;
}

__device__ __forceinline__ void cp16(uint32_t dst, const void* src) {
    asm volatile("cp.async.cg.shared.global [%0], [%1], 16;"
                 :: "r"(dst), "l"(src));
}
#define CP_COMMIT() asm volatile("cp.async.commit_group;" ::: "memory")
#define CP_WAIT()   asm volatile("cp.async.wait_group 1;"  ::: "memory")

__device__ __forceinline__ void ldm4(uint32_t* r, uint32_t addr) {
    asm volatile("ldmatrix.sync.aligned.m8n8.x4.shared.b16 {%0,%1,%2,%3}, [%4];"
                 : "=r"(r[0]), "=r"(r[1]), "=r"(r[2]), "=r"(r[3]) : "r"(addr));
}

__device__ __forceinline__ void mma16816(float* d, const uint32_t* a, const uint32_t* b) {
    asm volatile(
        "mma.sync.aligned.m16n8k16.row.col.f32.f16.f16.f32 "
        "{%0,%1,%2,%3}, {%4,%5,%6,%7}, {%8,%9}, {%0,%1,%2,%3};"
        : "+f"(d[0]), "+f"(d[1]), "+f"(d[2]), "+f"(d[3])
        : "r"(a[0]), "r"(a[1]), "r"(a[2]), "r"(a[3]), "r"(b[0]), "r"(b[1]));
}

// ----------------------------------------------------------------------------
// Kernel 1: fp32 -> fp16. Per thread: 4 independent float4 loads (MLP 4),
// packed into 2 coalesced uint4 stores. One uniform branch per block.
// Block covers 1024 float4 (16KB fp32 -> 8KB fp16). 4096 blocks per matrix.
// ----------------------------------------------------------------------------
__device__ __forceinline__ uint32_t pack2(float a, float b) {
    __half2 h = __floats2half2_rn(a, b);
    return *(const uint32_t*)&h;
}

__global__ void __launch_bounds__(256)
convert_half(const float* __restrict__ x, const float* __restrict__ W) {
    const bool isw = blockIdx.x >= 4096;
    const float4* __restrict__ src = (const float4*)(isw ? W : x);
    uint4* __restrict__ dst = (uint4*)(isw ? g_wh : g_xh);
    const int blk = isw ? blockIdx.x - 4096 : blockIdx.x;
    const int j0 = blk * 1024 + threadIdx.x * 2;   // float4 index
    const int d0 = blk * 512 + threadIdx.x;        // uint4 index (= j/2)

    float4 f0 = __ldcs(src + j0);
    float4 f1 = __ldcs(src + j0 + 1);
    float4 f2 = __ldcs(src + j0 + 512);
    float4 f3 = __ldcs(src + j0 + 513);

    uint4 o0, o1;
    o0.x = pack2(f0.x, f0.y); o0.y = pack2(f0.z, f0.w);
    o0.z = pack2(f1.x, f1.y); o0.w = pack2(f1.z, f1.w);
    o1.x = pack2(f2.x, f2.y); o1.y = pack2(f2.z, f2.w);
    o1.z = pack2(f3.x, f3.y); o1.w = pack2(f3.z, f3.w);

    __stcs(dst + d0, o0);
    __stcs(dst + d0 + 256, o1);
}

// ----------------------------------------------------------------------------
// Kernel 2: fp16 HMMA GEMM. BM=128 BN=128 BK=64, 3 stages, 4 warps (2x2),
// 2 CTAs per SM. Rows are 128B -> full 8-way SW128 swizzle.  (R13 verbatim.)
// ----------------------------------------------------------------------------
static constexpr int BM = 128;
static constexpr int BN = 128;
static constexpr int BK = 64;                    // fp16 elems (128B rows)
static constexpr int NK = DIM / BK;              // 64 iterations
static constexpr int NTHREADS = 128;

static constexpr int A_B = BM * BK * 2;          // 16384
static constexpr int B_B = BN * BK * 2;          // 16384
static constexpr int OFF_A = 0;
static constexpr int OFF_B = A_B;
static constexpr int STAGE_B = A_B + B_B;        // 32768
static constexpr int STAGES = 3;
static constexpr int SMEM_BYTES = STAGES * STAGE_B;  // 98304 -> 2 CTAs/SM

// SW128 swizzle: row r (128B rows), 16B unit u in [0,8)
__device__ __forceinline__ uint32_t sw_off(int r, int u) {
    return (uint32_t)(r * 128 + ((u ^ (r & 7)) << 4));
}

// 2048 cp16 per stage / 128 threads = 16 each (8 for A, 8 for B)
__device__ __forceinline__ void load_stage(uint32_t st, int tm, int tn, int k0, int tid) {
#pragma unroll
    for (int i = 0; i < 8; i++) {
        int c = tid + i * NTHREADS;
        int r = c >> 3, u = c & 7;
        cp16(st + OFF_A + sw_off(r, u),
             g_xh + (size_t)(tm * BM + r) * DIM + k0 + u * 8);
    }
#pragma unroll
    for (int i = 0; i < 8; i++) {
        int c = tid + i * NTHREADS;
        int r = c >> 3, u = c & 7;
        cp16(st + OFF_B + sw_off(r, u),
             g_wh + (size_t)(tn * BN + r) * DIM + k0 + u * 8);
    }
}

__global__ void __launch_bounds__(NTHREADS, 2)
gemm_kernel(const float* __restrict__ bias, float* __restrict__ out) {
    extern __shared__ char smem[];
    const uint32_t sb = smem_u32(smem);
    const int tid = threadIdx.x;
    const int wid = tid >> 5;
    const int lane = tid & 31;
    const int warp_m = wid & 1;      // 2 warps along M (64 rows each)
    const int warp_n = wid >> 1;     // 2 warps along N (64 cols each)

    // Grid: 32 tm x 32 tn = 1024 CTAs, tn-major.
    const int bid = blockIdx.x;
    const int tm = bid & 31;
    const int tn = bid >> 5;

    // ldmatrix lane addressing, 128B rows (proven fragment map).
    const int a_idx = lane >> 3;
    const int a_row = warp_m * 64 + (lane & 7) + (a_idx & 1) * 8;
    const int a_kk  = a_idx >> 1;
    const int b_idx = lane >> 3;
    const int b_row = warp_n * 64 + (lane & 7) + (b_idx >> 1) * 8;
    const int b_kk  = b_idx & 1;
    const int lsw   = lane & 7;

    uint32_t ua[4], ub[4];
#pragma unroll
    for (int ks = 0; ks < 4; ks++) {
        ua[ks] = (uint32_t)(((ks * 2 + a_kk) ^ lsw) << 4);
        ub[ks] = (uint32_t)(((ks * 2 + b_kk) ^ lsw) << 4);
    }
    const uint32_t a_base = (uint32_t)(a_row * 128);   // + mt*2048
    const uint32_t b_base = (uint32_t)(b_row * 128);   // + p*2048

    float acc[4][8][4];
#pragma unroll
    for (int mt = 0; mt < 4; mt++)
#pragma unroll
        for (int nt = 0; nt < 8; nt++)
#pragma unroll
            for (int j = 0; j < 4; j++) acc[mt][nt][j] = 0.f;

    // Prologue: fill STAGES-1 = 2 stages
#pragma unroll
    for (int s = 0; s < STAGES - 1; s++) {
        load_stage(sb + s * STAGE_B, tm, tn, s * BK, tid);
        CP_COMMIT();
    }

    int s_cur = 0;                  // stage of iteration kt
    int s_nxt = STAGES - 1;         // stage receiving kt + STAGES-1
    for (int kt = 0; kt < NK; kt++) {
        CP_WAIT();
        __syncthreads();

        // Issue next-stage loads first (that stage was last read at kt-1;
        // the barrier above makes the overwrite safe).
        const int kn = kt + STAGES - 1;
        if (kn < NK)
            load_stage(sb + s_nxt * STAGE_B, tm, tn, kn * BK, tid);
        CP_COMMIT();   // unconditional: keeps wait_group accounting exact

        const uint32_t stg = sb + s_cur * STAGE_B;
#pragma unroll
        for (int ks = 0; ks < 4; ks++) {
            uint32_t a[4][4];
#pragma unroll
            for (int mt = 0; mt < 4; mt++)
                ldm4(a[mt], stg + OFF_A + a_base + mt * 2048 + ua[ks]);
            uint32_t b[4][4];
#pragma unroll
            for (int p = 0; p < 4; p++)
                ldm4(b[p], stg + OFF_B + b_base + p * 2048 + ub[ks]);
#pragma unroll
            for (int mt = 0; mt < 4; mt++) {
#pragma unroll
                for (int nt = 0; nt < 8; nt++) {
                    const int p = nt >> 1, h = (nt & 1) * 2;
                    mma16816(acc[mt][nt], a[mt], &b[p][h]);
                }
            }
        }

        if (++s_cur == STAGES) s_cur = 0;
        if (++s_nxt == STAGES) s_nxt = 0;
    }

    // Epilogue: add bias, store fp32
    const int m0 = tm * BM + warp_m * 64;
    const int n0 = tn * BN + warp_n * 64;
    const int er = lane >> 2;
    const int ec = (lane & 3) * 2;
#pragma unroll
    for (int nt = 0; nt < 8; nt++) {
        const int col = n0 + nt * 8 + ec;
        const float b0 = __ldg(bias + col);
        const float b1 = __ldg(bias + col + 1);
#pragma unroll
        for (int mt = 0; mt < 4; mt++) {
            const int row = m0 + mt * 16 + er;
            float2 v0 = make_float2(acc[mt][nt][0] + b0, acc[mt][nt][1] + b1);
            float2 v1 = make_float2(acc[mt][nt][2] + b0, acc[mt][nt][3] + b1);
            *(float2*)(out + (size_t)row * DIM + col) = v0;
            *(float2*)(out + (size_t)(row + 8) * DIM + col) = v1;
        }
    }
}

// ----------------------------------------------------------------------------
// kernel_launch
// ----------------------------------------------------------------------------
extern "C" void kernel_launch(void* const* d_in, const int* in_sizes, int n_in,
                              void* d_out, int out_size) {
    const float* x = (const float*)d_in[0];
    const float* W = (const float*)d_in[1];
    const float* b = (const float*)d_in[2];
    float* out = (float*)d_out;

    cudaFuncSetAttribute(gemm_kernel,
                         cudaFuncAttributeMaxDynamicSharedMemorySize, SMEM_BYTES);

    convert_half<<<8192, 256>>>(x, W);

    const int grid = (DIM / BM) * (DIM / BN);   // 32 * 32 = 1024
    gemm_kernel<<<grid, NTHREADS, SMEM_BYTES>>>(b, out);
}